// round 1
// baseline (speedup 1.0000x reference)
#include <cuda_runtime.h>

// Problem constants (fixed by the problem instance; out_size == 512*512 confirms H,W).
#define SRC_N   128
#define PTS_N   2048
#define MIR_N   64
#define NCYL    16
#define NBOX    8
#define IMG_H   512
#define IMG_W   512
#define EXTENTF 12.0f
#define EPSF    1e-9f

#define TPB 256
#define TOTAL_RAYS (MIR_N * SRC_N * PTS_N)  // 16,777,216

struct CylS { float px, py, pz, ax, ay, az, L, r2; };
struct BoxS { float ax, ay, az, bx, by, bz; };

__global__ __launch_bounds__(TPB)
void render_kernel(
    const float* __restrict__ sources,      // [S,3]
    const float* __restrict__ mpts,         // [M,P,3]
    const float* __restrict__ mnrm,         // [M,P,3]
    const float* __restrict__ mpos,         // [M,3]
    const float* __restrict__ mrot,         // [M,3,3]
    const float* __restrict__ cyl_p1,       // [NC,3]
    const float* __restrict__ cyl_p2,       // [NC,3]
    const float* __restrict__ cyl_r,        // [NC]
    const float* __restrict__ box_p1,       // [NB,3]
    const float* __restrict__ box_p2,       // [NB,3]
    const float* __restrict__ spos,         // [3]
    const float* __restrict__ snrm,         // [3]
    float* __restrict__ img)                // [H,W]
{
    __shared__ CylS sc[NCYL];
    __shared__ BoxS sb[NBOX];
    __shared__ float ssp[3], ssn[3];

    const int tid = threadIdx.x;

    // Per-block scene setup: reduce cylinders to (p1, unit axis, length, r^2).
    if (tid < NCYL) {
        float p1x = cyl_p1[tid * 3 + 0];
        float p1y = cyl_p1[tid * 3 + 1];
        float p1z = cyl_p1[tid * 3 + 2];
        float axx = cyl_p2[tid * 3 + 0] - p1x;
        float axy = cyl_p2[tid * 3 + 1] - p1y;
        float axz = cyl_p2[tid * 3 + 2] - p1z;
        float L   = sqrtf(axx * axx + axy * axy + axz * axz);
        float il  = __fdividef(1.0f, L + EPSF);
        CylS c;
        c.px = p1x; c.py = p1y; c.pz = p1z;
        c.ax = axx * il; c.ay = axy * il; c.az = axz * il;
        c.L = L;
        float r = cyl_r[tid];
        c.r2 = r * r;
        sc[tid] = c;
    } else if (tid < NCYL + NBOX) {
        int b = tid - NCYL;
        BoxS bx;
        bx.ax = box_p1[b * 3 + 0]; bx.ay = box_p1[b * 3 + 1]; bx.az = box_p1[b * 3 + 2];
        bx.bx = box_p2[b * 3 + 0]; bx.by = box_p2[b * 3 + 1]; bx.bz = box_p2[b * 3 + 2];
        sb[b] = bx;
    } else if (tid < NCYL + NBOX + 3) {
        int c = tid - NCYL - NBOX;
        ssp[c] = spos[c];
        ssn[c] = snrm[c];
    }
    __syncthreads();

    const int idx = blockIdx.x * TPB + tid;
    // p fastest (2^11), then s (2^7), then m: block shares (m, s).
    const int m = idx >> 18;
    const int s = (idx >> 11) & (SRC_N - 1);
    const int p = idx & (PTS_N - 1);

    // Mirror transform (R, pos, source are block-uniform -> L1 broadcast).
    const float* Rm = mrot + m * 9;
    const float r00 = __ldg(Rm + 0), r01 = __ldg(Rm + 1), r02 = __ldg(Rm + 2);
    const float r10 = __ldg(Rm + 3), r11 = __ldg(Rm + 4), r12 = __ldg(Rm + 5);
    const float r20 = __ldg(Rm + 6), r21 = __ldg(Rm + 7), r22 = __ldg(Rm + 8);
    const float posx = __ldg(mpos + m * 3 + 0);
    const float posy = __ldg(mpos + m * 3 + 1);
    const float posz = __ldg(mpos + m * 3 + 2);

    const int mp = (m * PTS_N + p) * 3;
    const float ppx = __ldg(mpts + mp + 0);
    const float ppy = __ldg(mpts + mp + 1);
    const float ppz = __ldg(mpts + mp + 2);
    const float nnx = __ldg(mnrm + mp + 0);
    const float nny = __ldg(mnrm + mp + 1);
    const float nnz = __ldg(mnrm + mp + 2);

    const float tpx = r00 * ppx + r01 * ppy + r02 * ppz + posx;
    const float tpy = r10 * ppx + r11 * ppy + r12 * ppz + posy;
    const float tpz = r20 * ppx + r21 * ppy + r22 * ppz + posz;
    const float tnx = r00 * nnx + r01 * nny + r02 * nnz;
    const float tny = r10 * nnx + r11 * nny + r12 * nnz;
    const float tnz = r20 * nnx + r21 * nny + r22 * nnz;

    const float sx = __ldg(sources + s * 3 + 0);
    const float sy = __ldg(sources + s * 3 + 1);
    const float sz = __ldg(sources + s * 3 + 2);

    // Incident direction (source -> mirror point), normalized.
    float dx = tpx - sx, dy = tpy - sy, dz = tpz - sz;
    const float rin = rsqrtf(dx * dx + dy * dy + dz * dz);
    dx *= rin; dy *= rin; dz *= rin;

    const float dn = dx * tnx + dy * tny + dz * tnz;

    // Reflection and sensor-plane hit (cheap) -> early out-of-bounds rejection.
    const float rx = dx - 2.0f * dn * tnx;
    const float ry = dy - 2.0f * dn * tny;
    const float rz = dz - 2.0f * dn * tnz;
    const float snx = ssn[0], sny = ssn[1], snz = ssn[2];
    const float denom = rx * snx + ry * sny + rz * snz;
    const float tnum  = (ssp[0] - tpx) * snx + (ssp[1] - tpy) * sny + (ssp[2] - tpz) * snz;
    const float t = __fdividef(tnum, denom + EPSF);
    const float qx = tpx + t * rx;
    const float qy = tpy + t * ry;
    const float fx = (qx + EXTENTF) * ((float)IMG_W / (2.0f * EXTENTF));
    const float fy = (qy + EXTENTF) * ((float)IMG_H / (2.0f * EXTENTF));
    const float fix = floorf(fx);
    const float fiy = floorf(fy);
    if (!(fix >= 0.0f && fix < (float)IMG_W && fiy >= 0.0f && fiy < (float)IMG_H))
        return;
    const int ix = (int)fix;
    const int iy = (int)fiy;

    // Occlusion: ray from mirror point back toward the source, u = -d.
    const float ux = -dx, uy = -dy, uz = -dz;
    bool hit = false;

    // Boxes first (cheaper per test).
    {
        const float dux = (fabsf(ux) < EPSF) ? EPSF : ux;
        const float duy = (fabsf(uy) < EPSF) ? EPSF : uy;
        const float duz = (fabsf(uz) < EPSF) ? EPSF : uz;
        const float ivx = __fdividef(1.0f, dux);
        const float ivy = __fdividef(1.0f, duy);
        const float ivz = __fdividef(1.0f, duz);
        #pragma unroll
        for (int b = 0; b < NBOX; ++b) {
            const float t1x = (sb[b].ax - tpx) * ivx;
            const float t2x = (sb[b].bx - tpx) * ivx;
            const float t1y = (sb[b].ay - tpy) * ivy;
            const float t2y = (sb[b].by - tpy) * ivy;
            const float t1z = (sb[b].az - tpz) * ivz;
            const float t2z = (sb[b].bz - tpz) * ivz;
            const float tmin = fmaxf(fmaxf(fminf(t1x, t2x), fminf(t1y, t2y)), fminf(t1z, t2z));
            const float tmax = fminf(fminf(fmaxf(t1x, t2x), fmaxf(t1y, t2y)), fmaxf(t1z, t2z));
            if (tmax >= fmaxf(tmin, EPSF)) { hit = true; break; }
        }
    }

    if (!hit) {
        #pragma unroll 4
        for (int c = 0; c < NCYL; ++c) {
            const CylS cc = sc[c];
            const float ocx = tpx - cc.px;
            const float ocy = tpy - cc.py;
            const float ocz = tpz - cc.pz;
            const float ua = ux * cc.ax + uy * cc.ay + uz * cc.az;
            const float oa = ocx * cc.ax + ocy * cc.ay + ocz * cc.az;
            const float dvx = ux - ua * cc.ax;
            const float dvy = uy - ua * cc.ay;
            const float dvz = uz - ua * cc.az;
            const float mvx = ocx - oa * cc.ax;
            const float mvy = ocy - oa * cc.ay;
            const float mvz = ocz - oa * cc.az;
            const float A = dvx * dvx + dvy * dvy + dvz * dvz;
            const float B = 2.0f * (mvx * dvx + mvy * dvy + mvz * dvz);
            const float C = mvx * mvx + mvy * mvy + mvz * mvz - cc.r2;
            const float disc = B * B - 4.0f * A * C;
            if (disc > 0.0f) {
                const float sq  = sqrtf(disc);
                const float i2a = __fdividef(1.0f, 2.0f * A + EPSF);
                const float t1  = (-B - sq) * i2a;
                const float t2  = (-B + sq) * i2a;
                const float ax1 = oa + t1 * ua;
                const float ax2 = oa + t2 * ua;
                const bool h1 = (t1 > EPSF) && (ax1 >= 0.0f) && (ax1 <= cc.L);
                const bool h2 = (t2 > EPSF) && (ax2 >= 0.0f) && (ax2 <= cc.L);
                if (h1 || h2) { hit = true; break; }
            }
        }
    }

    if (hit) return;

    atomicAdd(&img[iy * IMG_W + ix], fabsf(dn));
}

extern "C" void kernel_launch(void* const* d_in, const int* in_sizes, int n_in,
                              void* d_out, int out_size) {
    const float* sources = (const float*)d_in[0];
    const float* mpts    = (const float*)d_in[1];
    const float* mnrm    = (const float*)d_in[2];
    const float* mpos    = (const float*)d_in[3];
    const float* mrot    = (const float*)d_in[4];
    const float* cyl_p1  = (const float*)d_in[5];
    const float* cyl_p2  = (const float*)d_in[6];
    const float* cyl_r   = (const float*)d_in[7];
    const float* box_p1  = (const float*)d_in[8];
    const float* box_p2  = (const float*)d_in[9];
    const float* spos    = (const float*)d_in[10];
    const float* snrm    = (const float*)d_in[11];
    float* img = (float*)d_out;

    cudaMemsetAsync(img, 0, (size_t)out_size * sizeof(float), 0);

    const int blocks = TOTAL_RAYS / TPB;
    render_kernel<<<blocks, TPB>>>(sources, mpts, mnrm, mpos, mrot,
                                   cyl_p1, cyl_p2, cyl_r, box_p1, box_p2,
                                   spos, snrm, img);
}

// round 2
// speedup vs baseline: 1.6008x; 1.6008x over previous
#include <cuda_runtime.h>

#define SRC_N   128
#define PTS_N   2048
#define MIR_N   64
#define NCYL    16
#define NBOX    8
#define IMG_H   512
#define IMG_W   512
#define EXTENTF 12.0f
#define EPSF    1e-9f

#define TPB 256
#define TOTAL_RAYS (MIR_N * SRC_N * PTS_N)   // 16,777,216
#define NPTS_TOTAL (MIR_N * PTS_N)           // 131,072

struct CylS { float px, py, pz, ax, ay, az, L, r2; };
struct BoxS { float ax, ay, az, bx, by, bz; };

// Precomputed transformed mirror points / normals (4 MB total, L2-resident).
__device__ float4 g_tp[NPTS_TOTAL];
__device__ float4 g_tn[NPTS_TOTAL];

// ---------------------------------------------------------------------------
// Pre-pass: transform mirror points/normals once per (m,p).
// ---------------------------------------------------------------------------
__global__ __launch_bounds__(TPB)
void transform_kernel(const float* __restrict__ mpts,
                      const float* __restrict__ mnrm,
                      const float* __restrict__ mpos,
                      const float* __restrict__ mrot)
{
    const int idx = blockIdx.x * TPB + threadIdx.x;
    if (idx >= NPTS_TOTAL) return;
    const int m = idx >> 11;            // PTS_N = 2048
    const float* Rm = mrot + m * 9;
    const float r00 = __ldg(Rm + 0), r01 = __ldg(Rm + 1), r02 = __ldg(Rm + 2);
    const float r10 = __ldg(Rm + 3), r11 = __ldg(Rm + 4), r12 = __ldg(Rm + 5);
    const float r20 = __ldg(Rm + 6), r21 = __ldg(Rm + 7), r22 = __ldg(Rm + 8);
    const float posx = __ldg(mpos + m * 3 + 0);
    const float posy = __ldg(mpos + m * 3 + 1);
    const float posz = __ldg(mpos + m * 3 + 2);

    const float ppx = __ldg(mpts + idx * 3 + 0);
    const float ppy = __ldg(mpts + idx * 3 + 1);
    const float ppz = __ldg(mpts + idx * 3 + 2);
    const float nnx = __ldg(mnrm + idx * 3 + 0);
    const float nny = __ldg(mnrm + idx * 3 + 1);
    const float nnz = __ldg(mnrm + idx * 3 + 2);

    float4 tp, tn;
    tp.x = r00 * ppx + r01 * ppy + r02 * ppz + posx;
    tp.y = r10 * ppx + r11 * ppy + r12 * ppz + posy;
    tp.z = r20 * ppx + r21 * ppy + r22 * ppz + posz;
    tp.w = 0.0f;
    tn.x = r00 * nnx + r01 * nny + r02 * nnz;
    tn.y = r10 * nnx + r11 * nny + r12 * nnz;
    tn.z = r20 * nnx + r21 * nny + r22 * nnz;
    tn.w = 0.0f;
    g_tp[idx] = tp;
    g_tn[idx] = tn;
}

// ---------------------------------------------------------------------------
// Main render kernel: one thread per ray, p fastest (block shares (m,s)).
// ---------------------------------------------------------------------------
__global__ __launch_bounds__(TPB)
void render_kernel(
    const float* __restrict__ sources,
    const float* __restrict__ cyl_p1,
    const float* __restrict__ cyl_p2,
    const float* __restrict__ cyl_r,
    const float* __restrict__ box_p1,
    const float* __restrict__ box_p2,
    const float* __restrict__ spos,
    const float* __restrict__ snrm,
    float* __restrict__ img)
{
    __shared__ CylS sc[NCYL];
    __shared__ BoxS sb[NBOX];
    __shared__ float ssp[3], ssn[3];
    __shared__ int s_allz;

    const int tid = threadIdx.x;

    if (tid < NCYL) {
        float p1x = cyl_p1[tid * 3 + 0];
        float p1y = cyl_p1[tid * 3 + 1];
        float p1z = cyl_p1[tid * 3 + 2];
        float axx = cyl_p2[tid * 3 + 0] - p1x;
        float axy = cyl_p2[tid * 3 + 1] - p1y;
        float axz = cyl_p2[tid * 3 + 2] - p1z;
        float L   = sqrtf(axx * axx + axy * axy + axz * axz);
        float il  = __fdividef(1.0f, L + EPSF);
        CylS c;
        c.px = p1x; c.py = p1y; c.pz = p1z;
        c.ax = axx * il; c.ay = axy * il; c.az = axz * il;
        c.L = L;
        float r = cyl_r[tid];
        c.r2 = r * r;
        sc[tid] = c;
    } else if (tid < NCYL + NBOX) {
        int b = tid - NCYL;
        BoxS bx;
        bx.ax = box_p1[b * 3 + 0]; bx.ay = box_p1[b * 3 + 1]; bx.az = box_p1[b * 3 + 2];
        bx.bx = box_p2[b * 3 + 0]; bx.by = box_p2[b * 3 + 1]; bx.bz = box_p2[b * 3 + 2];
        sb[b] = bx;
    } else if (tid < NCYL + NBOX + 3) {
        int c = tid - NCYL - NBOX;
        ssp[c] = spos[c];
        ssn[c] = snrm[c];
    }
    __syncthreads();
    if (tid == 0) {
        int allz = 1;
        #pragma unroll
        for (int c = 0; c < NCYL; ++c)
            if (!(sc[c].ax == 0.0f && sc[c].ay == 0.0f && sc[c].az > 0.0f)) allz = 0;
        s_allz = allz;
    }
    __syncthreads();

    const int idx = blockIdx.x * TPB + tid;
    const int m = idx >> 18;
    const int s = (idx >> 11) & (SRC_N - 1);
    const int p = idx & (PTS_N - 1);
    const int mpi = (m << 11) + p;

    const float4 tp4 = __ldg(&g_tp[mpi]);
    const float4 tn4 = __ldg(&g_tn[mpi]);
    const float tpx = tp4.x, tpy = tp4.y, tpz = tp4.z;
    const float tnx = tn4.x, tny = tn4.y, tnz = tn4.z;

    const float sx = __ldg(sources + s * 3 + 0);
    const float sy = __ldg(sources + s * 3 + 1);
    const float sz = __ldg(sources + s * 3 + 2);

    float dx = tpx - sx, dy = tpy - sy, dz = tpz - sz;
    const float rin = rsqrtf(dx * dx + dy * dy + dz * dz);
    dx *= rin; dy *= rin; dz *= rin;

    const float dn = dx * tnx + dy * tny + dz * tnz;

    // Reflection + sensor plane, then early OOB rejection.
    const float rx = dx - 2.0f * dn * tnx;
    const float ry = dy - 2.0f * dn * tny;
    const float rz = dz - 2.0f * dn * tnz;
    const float snx = ssn[0], sny = ssn[1], snz = ssn[2];
    const float denom = rx * snx + ry * sny + rz * snz;
    const float tnum  = (ssp[0] - tpx) * snx + (ssp[1] - tpy) * sny + (ssp[2] - tpz) * snz;
    const float t = __fdividef(tnum, denom + EPSF);
    const float qx = tpx + t * rx;
    const float qy = tpy + t * ry;
    const float fx = (qx + EXTENTF) * ((float)IMG_W / (2.0f * EXTENTF));
    const float fy = (qy + EXTENTF) * ((float)IMG_H / (2.0f * EXTENTF));
    const float fix = floorf(fx);
    const float fiy = floorf(fy);
    if (!(fix >= 0.0f && fix < (float)IMG_W && fiy >= 0.0f && fiy < (float)IMG_H))
        return;
    const int ix = (int)fix;
    const int iy = (int)fiy;

    // Shadow ray: u = -d.
    const float ux = -dx, uy = -dy, uz = -dz;
    bool hit = false;

    // Boxes.
    {
        const float dux = (fabsf(ux) < EPSF) ? EPSF : ux;
        const float duy = (fabsf(uy) < EPSF) ? EPSF : uy;
        const float duz = (fabsf(uz) < EPSF) ? EPSF : uz;
        const float ivx = __fdividef(1.0f, dux);
        const float ivy = __fdividef(1.0f, duy);
        const float ivz = __fdividef(1.0f, duz);
        const float ox = tpx * ivx, oy = tpy * ivy, oz = tpz * ivz;
        #pragma unroll
        for (int b = 0; b < NBOX; ++b) {
            const float t1x = fmaf(sb[b].ax, ivx, -ox);
            const float t2x = fmaf(sb[b].bx, ivx, -ox);
            const float t1y = fmaf(sb[b].ay, ivy, -oy);
            const float t2y = fmaf(sb[b].by, ivy, -oy);
            const float t1z = fmaf(sb[b].az, ivz, -oz);
            const float t2z = fmaf(sb[b].bz, ivz, -oz);
            const float tmin = fmaxf(fmaxf(fminf(t1x, t2x), fminf(t1y, t2y)), fminf(t1z, t2z));
            const float tmax = fminf(fminf(fmaxf(t1x, t2x), fmaxf(t1y, t2y)), fmaxf(t1z, t2z));
            if (tmax >= fmaxf(tmin, EPSF)) { hit = true; break; }
        }
    }

    if (!hit) {
        if (s_allz) {
            // Specialized path: all cylinder axes are exactly +z, unit length axis.
            // With |u|=1: A = ux^2+uy^2 (ray-invariant), quadratic in 2D.
            const float A2  = ux * ux + uy * uy;
            const float i2a = __fdividef(1.0f, A2 + EPSF);
            #pragma unroll 4
            for (int c = 0; c < NCYL; ++c) {
                const float mx = tpx - sc[c].px;
                const float my = tpy - sc[c].py;
                const float Bh = mx * ux + my * uy;              // B/2
                const float C  = fmaf(mx, mx, my * my) - sc[c].r2;
                const float d4 = fmaf(Bh, Bh, -A2 * C);          // disc/4
                if (d4 > 0.0f) {
                    const float sq = sqrtf(d4);
                    const float t1 = (-Bh - sq) * i2a;
                    const float t2 = (-Bh + sq) * i2a;
                    const float oa = tpz - sc[c].pz;
                    const float a1 = fmaf(t1, uz, oa);
                    const float a2 = fmaf(t2, uz, oa);
                    const bool h1 = (t1 > EPSF) & (a1 >= 0.0f) & (a1 <= sc[c].L);
                    const bool h2 = (t2 > EPSF) & (a2 >= 0.0f) & (a2 <= sc[c].L);
                    if (h1 | h2) { hit = true; break; }
                }
            }
        } else {
            // General fallback (block-uniform branch; uses |u|=1 identities).
            #pragma unroll 4
            for (int c = 0; c < NCYL; ++c) {
                const CylS cc = sc[c];
                const float ocx = tpx - cc.px;
                const float ocy = tpy - cc.py;
                const float ocz = tpz - cc.pz;
                const float ua  = ux * cc.ax + uy * cc.ay + uz * cc.az;
                const float oa  = ocx * cc.ax + ocy * cc.ay + ocz * cc.az;
                const float ocu = ocx * ux + ocy * uy + ocz * uz;
                const float oc2 = ocx * ocx + ocy * ocy + ocz * ocz;
                const float A   = 1.0f - ua * ua;
                const float Bh  = ocu - oa * ua;                 // B/2
                const float C   = oc2 - oa * oa - cc.r2;
                const float d4  = fmaf(Bh, Bh, -A * C);
                if (d4 > 0.0f) {
                    const float sq  = sqrtf(d4);
                    const float i2a = __fdividef(1.0f, A + EPSF);
                    const float t1  = (-Bh - sq) * i2a;
                    const float t2  = (-Bh + sq) * i2a;
                    const float a1  = fmaf(t1, ua, oa);
                    const float a2  = fmaf(t2, ua, oa);
                    const bool h1 = (t1 > EPSF) & (a1 >= 0.0f) & (a1 <= cc.L);
                    const bool h2 = (t2 > EPSF) & (a2 >= 0.0f) & (a2 <= cc.L);
                    if (h1 | h2) { hit = true; break; }
                }
            }
        }
    }

    if (hit) return;

    atomicAdd(&img[iy * IMG_W + ix], fabsf(dn));
}

extern "C" void kernel_launch(void* const* d_in, const int* in_sizes, int n_in,
                              void* d_out, int out_size) {
    const float* sources = (const float*)d_in[0];
    const float* mpts    = (const float*)d_in[1];
    const float* mnrm    = (const float*)d_in[2];
    const float* mpos    = (const float*)d_in[3];
    const float* mrot    = (const float*)d_in[4];
    const float* cyl_p1  = (const float*)d_in[5];
    const float* cyl_p2  = (const float*)d_in[6];
    const float* cyl_r   = (const float*)d_in[7];
    const float* box_p1  = (const float*)d_in[8];
    const float* box_p2  = (const float*)d_in[9];
    const float* spos    = (const float*)d_in[10];
    const float* snrm    = (const float*)d_in[11];
    float* img = (float*)d_out;

    cudaMemsetAsync(img, 0, (size_t)out_size * sizeof(float), 0);

    transform_kernel<<<NPTS_TOTAL / TPB, TPB>>>(mpts, mnrm, mpos, mrot);

    render_kernel<<<TOTAL_RAYS / TPB, TPB>>>(sources,
                                             cyl_p1, cyl_p2, cyl_r,
                                             box_p1, box_p2,
                                             spos, snrm, img);
}

// round 3
// speedup vs baseline: 2.2415x; 1.4003x over previous
#include <cuda_runtime.h>

#define SRC_N   128
#define PTS_N   2048
#define MIR_N   64
#define NCYL    16
#define NBOX    8
#define IMG_H   512
#define IMG_W   512
#define EXTENTF 12.0f
#define EPSF    1e-9f

#define TPB 256
#define TOTAL_RAYS (MIR_N * SRC_N * PTS_N)   // 16,777,216
#define NPTS_TOTAL (MIR_N * PTS_N)           // 131,072

// Conservative mirror-footprint radius in xy (exact bound 0.84853) + margin.
#define RMIR    0.87f
#define RMARG   0.02f

struct CylS { float px, py, pz, ax, ay, az, L, r2; };

// Precomputed transformed mirror points / normals (4 MB, L2-resident).
__device__ float4 g_tp[NPTS_TOTAL];
__device__ float4 g_tn[NPTS_TOTAL];

// ---------------------------------------------------------------------------
// Pre-pass: transform mirror points/normals once per (m,p).
// ---------------------------------------------------------------------------
__global__ __launch_bounds__(TPB)
void transform_kernel(const float* __restrict__ mpts,
                      const float* __restrict__ mnrm,
                      const float* __restrict__ mpos,
                      const float* __restrict__ mrot)
{
    const int idx = blockIdx.x * TPB + threadIdx.x;
    if (idx >= NPTS_TOTAL) return;
    const int m = idx >> 11;
    const float* Rm = mrot + m * 9;
    const float r00 = __ldg(Rm + 0), r01 = __ldg(Rm + 1), r02 = __ldg(Rm + 2);
    const float r10 = __ldg(Rm + 3), r11 = __ldg(Rm + 4), r12 = __ldg(Rm + 5);
    const float r20 = __ldg(Rm + 6), r21 = __ldg(Rm + 7), r22 = __ldg(Rm + 8);
    const float posx = __ldg(mpos + m * 3 + 0);
    const float posy = __ldg(mpos + m * 3 + 1);
    const float posz = __ldg(mpos + m * 3 + 2);

    const float ppx = __ldg(mpts + idx * 3 + 0);
    const float ppy = __ldg(mpts + idx * 3 + 1);
    const float ppz = __ldg(mpts + idx * 3 + 2);
    const float nnx = __ldg(mnrm + idx * 3 + 0);
    const float nny = __ldg(mnrm + idx * 3 + 1);
    const float nnz = __ldg(mnrm + idx * 3 + 2);

    float4 tp, tn;
    tp.x = r00 * ppx + r01 * ppy + r02 * ppz + posx;
    tp.y = r10 * ppx + r11 * ppy + r12 * ppz + posy;
    tp.z = r20 * ppx + r21 * ppy + r22 * ppz + posz;
    tp.w = 0.0f;
    tn.x = r00 * nnx + r01 * nny + r02 * nnz;
    tn.y = r10 * nnx + r11 * nny + r12 * nnz;
    tn.z = r20 * nnx + r21 * nny + r22 * nnz;
    tn.w = 0.0f;
    g_tp[idx] = tp;
    g_tn[idx] = tn;
}

// ---------------------------------------------------------------------------
// Main render kernel: one thread per ray, p fastest (block shares (m,s)).
// Per-block conservative occluder culling: every ray passes through source s
// and starts within RMIR (xy) of the mirror position -> 2D pencil bound.
// ---------------------------------------------------------------------------
__global__ __launch_bounds__(TPB)
void render_kernel(
    const float* __restrict__ sources,
    const float* __restrict__ mpos,
    const float* __restrict__ cyl_p1,
    const float* __restrict__ cyl_p2,
    const float* __restrict__ cyl_r,
    const float* __restrict__ box_p1,
    const float* __restrict__ box_p2,
    const float* __restrict__ spos,
    const float* __restrict__ snrm,
    float* __restrict__ img)
{
    __shared__ float4 scyl[NCYL];     // (px, py, pz, r^2)  (compacted if allz)
    __shared__ float  scylL[NCYL];    // axis length
    __shared__ CylS   scg[NCYL];      // general fallback data (uncompacted)
    __shared__ float4 sbA[NBOX];      // (ax, ay, az, bx)   (compacted)
    __shared__ float4 sbB[NBOX];      // (by, bz, -, -)
    __shared__ int    sflag[NCYL + NBOX];
    __shared__ int    s_azf[NCYL];
    __shared__ int    s_ncyl, s_nbox, s_allz;
    __shared__ float  ssp[3], ssn[3];

    const int tid  = threadIdx.x;
    const int base = blockIdx.x * TPB;
    const int m = base >> 18;
    const int s = (base >> 11) & (SRC_N - 1);

    if (tid < NCYL) {
        const float p1x = cyl_p1[tid * 3 + 0];
        const float p1y = cyl_p1[tid * 3 + 1];
        const float p1z = cyl_p1[tid * 3 + 2];
        float axx = cyl_p2[tid * 3 + 0] - p1x;
        float axy = cyl_p2[tid * 3 + 1] - p1y;
        float axz = cyl_p2[tid * 3 + 2] - p1z;
        const float L  = sqrtf(axx * axx + axy * axy + axz * axz);
        const float il = __fdividef(1.0f, L + EPSF);
        const float uax = axx * il, uay = axy * il, uaz = axz * il;
        const float r = cyl_r[tid];

        CylS c;
        c.px = p1x; c.py = p1y; c.pz = p1z;
        c.ax = uax; c.ay = uay; c.az = uaz;
        c.L = L; c.r2 = r * r;
        scg[tid] = c;
        s_azf[tid] = (uax == 0.0f && uay == 0.0f && uaz > 0.0f) ? 1 : 0;
        scyl[tid]  = make_float4(p1x, p1y, p1z, r * r);
        scylL[tid] = L;

        // Conservative pencil cull (2D, through source).
        const float sx = sources[s * 3 + 0], sy = sources[s * 3 + 1];
        const float cx = mpos[m * 3 + 0],    cy = mpos[m * 3 + 1];
        const float qxs = p1x - sx, qys = p1y - sy;
        const float cxs = cx - sx,  cys = cy - sy;
        const float crs = fabsf(qxs * cys - qys * cxs);
        const float dqs = sqrtf(qxs * qxs + qys * qys);
        const float dcs = sqrtf(cxs * cxs + cys * cys);
        const int cull = (crs - dqs * RMIR) > (r + RMARG) * (dcs + RMIR);
        sflag[tid] = !cull;
    } else if (tid < NCYL + NBOX) {
        const int b = tid - NCYL;
        const float ax = box_p1[b * 3 + 0], ay = box_p1[b * 3 + 1], az = box_p1[b * 3 + 2];
        const float bx = box_p2[b * 3 + 0], by = box_p2[b * 3 + 1], bz = box_p2[b * 3 + 2];
        sbA[b] = make_float4(ax, ay, az, bx);
        sbB[b] = make_float4(by, bz, 0.0f, 0.0f);

        const float sx = sources[s * 3 + 0], sy = sources[s * 3 + 1];
        const float cx = mpos[m * 3 + 0],    cy = mpos[m * 3 + 1];
        const float bcx = 0.5f * (ax + bx), bcy = 0.5f * (ay + by);
        const float reff = 0.5f * sqrtf((bx - ax) * (bx - ax) + (by - ay) * (by - ay));
        const float qxs = bcx - sx, qys = bcy - sy;
        const float cxs = cx - sx,  cys = cy - sy;
        const float crs = fabsf(qxs * cys - qys * cxs);
        const float dqs = sqrtf(qxs * qxs + qys * qys);
        const float dcs = sqrtf(cxs * cxs + cys * cys);
        const int cull = (crs - dqs * RMIR) > (reff + RMARG) * (dcs + RMIR);
        sflag[tid] = !cull;
    } else if (tid < NCYL + NBOX + 3) {
        const int c = tid - NCYL - NBOX;
        ssp[c] = spos[c];
        ssn[c] = snrm[c];
    }
    __syncthreads();

    if (tid == 0) {
        int allz = 1;
        #pragma unroll
        for (int c = 0; c < NCYL; ++c) allz &= s_azf[c];
        s_allz = allz;
        int n = 0;
        if (allz) {                      // compacted fast list only valid if vertical
            for (int c = 0; c < NCYL; ++c) {
                if (sflag[c]) { scyl[n] = scyl[c]; scylL[n] = scylL[c]; ++n; }
            }
        } else {
            n = NCYL;                    // fallback iterates scg fully
        }
        s_ncyl = n;
        int nb = 0;
        for (int b = 0; b < NBOX; ++b) {
            if (sflag[NCYL + b]) { sbA[nb] = sbA[b]; sbB[nb] = sbB[b]; ++nb; }
        }
        s_nbox = nb;
    }
    __syncthreads();

    const int idx = base + tid;
    const int p = idx & (PTS_N - 1);
    const int mpi = (m << 11) + p;

    const float4 tp4 = __ldg(&g_tp[mpi]);
    const float4 tn4 = __ldg(&g_tn[mpi]);
    const float tpx = tp4.x, tpy = tp4.y, tpz = tp4.z;
    const float tnx = tn4.x, tny = tn4.y, tnz = tn4.z;

    const float sx = __ldg(sources + s * 3 + 0);
    const float sy = __ldg(sources + s * 3 + 1);
    const float sz = __ldg(sources + s * 3 + 2);

    float dx = tpx - sx, dy = tpy - sy, dz = tpz - sz;
    const float rin = rsqrtf(dx * dx + dy * dy + dz * dz);
    dx *= rin; dy *= rin; dz *= rin;

    const float dn = dx * tnx + dy * tny + dz * tnz;

    // Reflection + sensor plane, early OOB rejection.
    const float rx = dx - 2.0f * dn * tnx;
    const float ry = dy - 2.0f * dn * tny;
    const float rz = dz - 2.0f * dn * tnz;
    const float snx = ssn[0], sny = ssn[1], snz = ssn[2];
    const float denom = rx * snx + ry * sny + rz * snz;
    const float tnum  = (ssp[0] - tpx) * snx + (ssp[1] - tpy) * sny + (ssp[2] - tpz) * snz;
    const float t = __fdividef(tnum, denom + EPSF);
    const float qx = tpx + t * rx;
    const float qy = tpy + t * ry;
    const float fx = (qx + EXTENTF) * ((float)IMG_W / (2.0f * EXTENTF));
    const float fy = (qy + EXTENTF) * ((float)IMG_H / (2.0f * EXTENTF));
    const float fix = floorf(fx);
    const float fiy = floorf(fy);
    if (!(fix >= 0.0f && fix < (float)IMG_W && fiy >= 0.0f && fiy < (float)IMG_H))
        return;
    const int ix = (int)fix;
    const int iy = (int)fiy;

    // Shadow ray: u = -d.
    const float ux = -dx, uy = -dy, uz = -dz;
    bool hit = false;

    // Surviving boxes.
    const int nbox = s_nbox;
    if (nbox > 0) {
        const float dux = (fabsf(ux) < EPSF) ? EPSF : ux;
        const float duy = (fabsf(uy) < EPSF) ? EPSF : uy;
        const float duz = (fabsf(uz) < EPSF) ? EPSF : uz;
        const float ivx = __fdividef(1.0f, dux);
        const float ivy = __fdividef(1.0f, duy);
        const float ivz = __fdividef(1.0f, duz);
        const float ox = tpx * ivx, oy = tpy * ivy, oz = tpz * ivz;
        for (int b = 0; b < nbox; ++b) {
            const float4 A = sbA[b];
            const float4 B = sbB[b];
            const float t1x = fmaf(A.x, ivx, -ox);
            const float t2x = fmaf(A.w, ivx, -ox);
            const float t1y = fmaf(A.y, ivy, -oy);
            const float t2y = fmaf(B.x, ivy, -oy);
            const float t1z = fmaf(A.z, ivz, -oz);
            const float t2z = fmaf(B.y, ivz, -oz);
            const float tmin = fmaxf(fmaxf(fminf(t1x, t2x), fminf(t1y, t2y)), fminf(t1z, t2z));
            const float tmax = fminf(fminf(fmaxf(t1x, t2x), fmaxf(t1y, t2y)), fmaxf(t1z, t2z));
            if (tmax >= fmaxf(tmin, EPSF)) { hit = true; break; }
        }
    }

    if (!hit) {
        const int ncyl = s_ncyl;
        if (s_allz) {
            // Vertical cylinders: 2D quadratic, A = ux^2+uy^2 (ray-invariant).
            const float A2  = ux * ux + uy * uy;
            const float i2a = __fdividef(1.0f, A2 + EPSF);
            for (int c = 0; c < ncyl; ++c) {
                const float4 cc = scyl[c];
                const float mx = tpx - cc.x;
                const float my = tpy - cc.y;
                const float Bh = mx * ux + my * uy;
                const float C  = fmaf(mx, mx, my * my) - cc.w;
                const float d4 = fmaf(Bh, Bh, -A2 * C);
                if (d4 > 0.0f) {
                    const float sq = sqrtf(d4);
                    const float t1 = (-Bh - sq) * i2a;
                    const float t2 = (-Bh + sq) * i2a;
                    const float oa = tpz - cc.z;
                    const float a1 = fmaf(t1, uz, oa);
                    const float a2 = fmaf(t2, uz, oa);
                    const float L  = scylL[c];
                    const bool h1 = (t1 > EPSF) & (a1 >= 0.0f) & (a1 <= L);
                    const bool h2 = (t2 > EPSF) & (a2 >= 0.0f) & (a2 <= L);
                    if (h1 | h2) { hit = true; break; }
                }
            }
        } else {
            // General fallback (uses |u|=1 identities), no culling.
            for (int c = 0; c < NCYL; ++c) {
                const CylS cc = scg[c];
                const float ocx = tpx - cc.px;
                const float ocy = tpy - cc.py;
                const float ocz = tpz - cc.pz;
                const float ua  = ux * cc.ax + uy * cc.ay + uz * cc.az;
                const float oa  = ocx * cc.ax + ocy * cc.ay + ocz * cc.az;
                const float ocu = ocx * ux + ocy * uy + ocz * uz;
                const float oc2 = ocx * ocx + ocy * ocy + ocz * ocz;
                const float A   = 1.0f - ua * ua;
                const float Bh  = ocu - oa * ua;
                const float C   = oc2 - oa * oa - cc.r2;
                const float d4  = fmaf(Bh, Bh, -A * C);
                if (d4 > 0.0f) {
                    const float sq  = sqrtf(d4);
                    const float i2a = __fdividef(1.0f, A + EPSF);
                    const float t1  = (-Bh - sq) * i2a;
                    const float t2  = (-Bh + sq) * i2a;
                    const float a1  = fmaf(t1, ua, oa);
                    const float a2  = fmaf(t2, ua, oa);
                    const bool h1 = (t1 > EPSF) & (a1 >= 0.0f) & (a1 <= cc.L);
                    const bool h2 = (t2 > EPSF) & (a2 >= 0.0f) & (a2 <= cc.L);
                    if (h1 | h2) { hit = true; break; }
                }
            }
        }
    }

    if (hit) return;

    atomicAdd(&img[iy * IMG_W + ix], fabsf(dn));
}

extern "C" void kernel_launch(void* const* d_in, const int* in_sizes, int n_in,
                              void* d_out, int out_size) {
    const float* sources = (const float*)d_in[0];
    const float* mpts    = (const float*)d_in[1];
    const float* mnrm    = (const float*)d_in[2];
    const float* mpos    = (const float*)d_in[3];
    const float* mrot    = (const float*)d_in[4];
    const float* cyl_p1  = (const float*)d_in[5];
    const float* cyl_p2  = (const float*)d_in[6];
    const float* cyl_r   = (const float*)d_in[7];
    const float* box_p1  = (const float*)d_in[8];
    const float* box_p2  = (const float*)d_in[9];
    const float* spos    = (const float*)d_in[10];
    const float* snrm    = (const float*)d_in[11];
    float* img = (float*)d_out;

    cudaMemsetAsync(img, 0, (size_t)out_size * sizeof(float), 0);

    transform_kernel<<<NPTS_TOTAL / TPB, TPB>>>(mpts, mnrm, mpos, mrot);

    render_kernel<<<TOTAL_RAYS / TPB, TPB>>>(sources, mpos,
                                             cyl_p1, cyl_p2, cyl_r,
                                             box_p1, box_p2,
                                             spos, snrm, img);
}

// round 4
// speedup vs baseline: 2.5710x; 1.1470x over previous
#include <cuda_runtime.h>

#define SRC_N   128
#define PTS_N   2048
#define MIR_N   64
#define NCYL    16
#define NBOX    8
#define IMG_H   512
#define IMG_W   512
#define EXTENTF 12.0f
#define EPSF    1e-9f

#define TPB 256
#define RPT 2                                // rays per thread
#define RPB (TPB * RPT)                      // 512 rays per block
#define TOTAL_RAYS (MIR_N * SRC_N * PTS_N)   // 16,777,216
#define NPTS_TOTAL (MIR_N * PTS_N)           // 131,072

// Conservative mirror-footprint radius in xy (exact bound 0.84853) + margin.
#define RMIR    0.87f
#define RMARG   0.02f

struct CylS { float px, py, pz, ax, ay, az, L, r2; };

// Precomputed transformed mirror points / normals (4 MB, L2-resident).
__device__ float4 g_tp[NPTS_TOTAL];
__device__ float4 g_tn[NPTS_TOTAL];

// ---------------------------------------------------------------------------
// Pre-pass: transform mirror points/normals once per (m,p).
// ---------------------------------------------------------------------------
__global__ __launch_bounds__(TPB)
void transform_kernel(const float* __restrict__ mpts,
                      const float* __restrict__ mnrm,
                      const float* __restrict__ mpos,
                      const float* __restrict__ mrot)
{
    const int idx = blockIdx.x * TPB + threadIdx.x;
    if (idx >= NPTS_TOTAL) return;
    const int m = idx >> 11;
    const float* Rm = mrot + m * 9;
    const float r00 = __ldg(Rm + 0), r01 = __ldg(Rm + 1), r02 = __ldg(Rm + 2);
    const float r10 = __ldg(Rm + 3), r11 = __ldg(Rm + 4), r12 = __ldg(Rm + 5);
    const float r20 = __ldg(Rm + 6), r21 = __ldg(Rm + 7), r22 = __ldg(Rm + 8);
    const float posx = __ldg(mpos + m * 3 + 0);
    const float posy = __ldg(mpos + m * 3 + 1);
    const float posz = __ldg(mpos + m * 3 + 2);

    const float ppx = __ldg(mpts + idx * 3 + 0);
    const float ppy = __ldg(mpts + idx * 3 + 1);
    const float ppz = __ldg(mpts + idx * 3 + 2);
    const float nnx = __ldg(mnrm + idx * 3 + 0);
    const float nny = __ldg(mnrm + idx * 3 + 1);
    const float nnz = __ldg(mnrm + idx * 3 + 2);

    float4 tp, tn;
    tp.x = r00 * ppx + r01 * ppy + r02 * ppz + posx;
    tp.y = r10 * ppx + r11 * ppy + r12 * ppz + posy;
    tp.z = r20 * ppx + r21 * ppy + r22 * ppz + posz;
    tp.w = 0.0f;
    tn.x = r00 * nnx + r01 * nny + r02 * nnz;
    tn.y = r10 * nnx + r11 * nny + r12 * nnz;
    tn.z = r20 * nnx + r21 * nny + r22 * nnz;
    tn.w = 0.0f;
    g_tp[idx] = tp;
    g_tn[idx] = tn;
}

// ---------------------------------------------------------------------------
// Main render kernel: 2 rays per thread (independent chains -> ILP),
// block shares (m,s); conservative per-block occluder culling.
// ---------------------------------------------------------------------------
__global__ __launch_bounds__(TPB)
void render_kernel(
    const float* __restrict__ sources,
    const float* __restrict__ mpos,
    const float* __restrict__ cyl_p1,
    const float* __restrict__ cyl_p2,
    const float* __restrict__ cyl_r,
    const float* __restrict__ box_p1,
    const float* __restrict__ box_p2,
    const float* __restrict__ spos,
    const float* __restrict__ snrm,
    float* __restrict__ img)
{
    __shared__ float4 scyl[NCYL];     // (px, py, pz, r^2)  (compacted if allz)
    __shared__ float  scylL[NCYL];
    __shared__ CylS   scg[NCYL];      // general fallback (uncompacted)
    __shared__ float4 sbA[NBOX];      // (ax, ay, az, bx)   (compacted)
    __shared__ float4 sbB[NBOX];      // (by, bz, -, -)
    __shared__ int    sflag[NCYL + NBOX];
    __shared__ int    s_azf[NCYL];
    __shared__ int    s_ncyl, s_nbox, s_allz;
    __shared__ float  ssp[3], ssn[3];

    const int tid  = threadIdx.x;
    const int base = blockIdx.x * RPB;
    const int m = base >> 18;
    const int s = (base >> 11) & (SRC_N - 1);

    if (tid < NCYL) {
        const float p1x = cyl_p1[tid * 3 + 0];
        const float p1y = cyl_p1[tid * 3 + 1];
        const float p1z = cyl_p1[tid * 3 + 2];
        float axx = cyl_p2[tid * 3 + 0] - p1x;
        float axy = cyl_p2[tid * 3 + 1] - p1y;
        float axz = cyl_p2[tid * 3 + 2] - p1z;
        const float L  = sqrtf(axx * axx + axy * axy + axz * axz);
        const float il = __fdividef(1.0f, L + EPSF);
        const float uax = axx * il, uay = axy * il, uaz = axz * il;
        const float r = cyl_r[tid];

        CylS c;
        c.px = p1x; c.py = p1y; c.pz = p1z;
        c.ax = uax; c.ay = uay; c.az = uaz;
        c.L = L; c.r2 = r * r;
        scg[tid] = c;
        s_azf[tid] = (uax == 0.0f && uay == 0.0f && uaz > 0.0f) ? 1 : 0;
        scyl[tid]  = make_float4(p1x, p1y, p1z, r * r);
        scylL[tid] = L;

        const float sx = sources[s * 3 + 0], sy = sources[s * 3 + 1];
        const float cx = mpos[m * 3 + 0],    cy = mpos[m * 3 + 1];
        const float qxs = p1x - sx, qys = p1y - sy;
        const float cxs = cx - sx,  cys = cy - sy;
        const float crs = fabsf(qxs * cys - qys * cxs);
        const float dqs = sqrtf(qxs * qxs + qys * qys);
        const float dcs = sqrtf(cxs * cxs + cys * cys);
        const int cull = (crs - dqs * RMIR) > (r + RMARG) * (dcs + RMIR);
        sflag[tid] = !cull;
    } else if (tid < NCYL + NBOX) {
        const int b = tid - NCYL;
        const float ax = box_p1[b * 3 + 0], ay = box_p1[b * 3 + 1], az = box_p1[b * 3 + 2];
        const float bx = box_p2[b * 3 + 0], by = box_p2[b * 3 + 1], bz = box_p2[b * 3 + 2];
        sbA[b] = make_float4(ax, ay, az, bx);
        sbB[b] = make_float4(by, bz, 0.0f, 0.0f);

        const float sx = sources[s * 3 + 0], sy = sources[s * 3 + 1];
        const float cx = mpos[m * 3 + 0],    cy = mpos[m * 3 + 1];
        const float bcx = 0.5f * (ax + bx), bcy = 0.5f * (ay + by);
        const float reff = 0.5f * sqrtf((bx - ax) * (bx - ax) + (by - ay) * (by - ay));
        const float qxs = bcx - sx, qys = bcy - sy;
        const float cxs = cx - sx,  cys = cy - sy;
        const float crs = fabsf(qxs * cys - qys * cxs);
        const float dqs = sqrtf(qxs * qxs + qys * qys);
        const float dcs = sqrtf(cxs * cxs + cys * cys);
        const int cull = (crs - dqs * RMIR) > (reff + RMARG) * (dcs + RMIR);
        sflag[tid] = !cull;
    } else if (tid < NCYL + NBOX + 3) {
        const int c = tid - NCYL - NBOX;
        ssp[c] = spos[c];
        ssn[c] = snrm[c];
    }
    __syncthreads();

    if (tid == 0) {
        int allz = 1;
        #pragma unroll
        for (int c = 0; c < NCYL; ++c) allz &= s_azf[c];
        s_allz = allz;
        int n = 0;
        if (allz) {
            for (int c = 0; c < NCYL; ++c) {
                if (sflag[c]) { scyl[n] = scyl[c]; scylL[n] = scylL[c]; ++n; }
            }
        } else {
            n = NCYL;
        }
        s_ncyl = n;
        int nb = 0;
        for (int b = 0; b < NBOX; ++b) {
            if (sflag[NCYL + b]) { sbA[nb] = sbA[b]; sbB[nb] = sbB[b]; ++nb; }
        }
        s_nbox = nb;
    }
    __syncthreads();

    const float sx = __ldg(sources + s * 3 + 0);
    const float sy = __ldg(sources + s * 3 + 1);
    const float sz = __ldg(sources + s * 3 + 2);
    const float snx = ssn[0], sny = ssn[1], snz = ssn[2];
    const float sp0 = ssp[0], sp1 = ssp[1], sp2 = ssp[2];

    const int p0 = (base & (PTS_N - 1)) + tid;     // p for ray 0 (ray 1: +TPB)
    const int mbase = (m << 11);

    // ---- Stage 1: per-ray setup (two independent chains) ----
    float TPX[RPT], TPY[RPT], TPZ[RPT];
    float UX[RPT], UY[RPT], UZ[RPT];
    float VAL[RPT];
    int   PIX[RPT];
    bool  OK[RPT];

    #pragma unroll
    for (int r = 0; r < RPT; ++r) {
        const int mpi = mbase + p0 + r * TPB;
        const float4 tp4 = __ldg(&g_tp[mpi]);
        const float4 tn4 = __ldg(&g_tn[mpi]);
        const float tpx = tp4.x, tpy = tp4.y, tpz = tp4.z;

        float dx = tpx - sx, dy = tpy - sy, dz = tpz - sz;
        const float rin = rsqrtf(dx * dx + dy * dy + dz * dz);
        dx *= rin; dy *= rin; dz *= rin;

        const float dn = dx * tn4.x + dy * tn4.y + dz * tn4.z;

        const float rx = dx - 2.0f * dn * tn4.x;
        const float ry = dy - 2.0f * dn * tn4.y;
        const float rz = dz - 2.0f * dn * tn4.z;
        const float denom = rx * snx + ry * sny + rz * snz;
        const float tnum  = (sp0 - tpx) * snx + (sp1 - tpy) * sny + (sp2 - tpz) * snz;
        const float t = __fdividef(tnum, denom + EPSF);
        const float qx = tpx + t * rx;
        const float qy = tpy + t * ry;
        const float fx = (qx + EXTENTF) * ((float)IMG_W / (2.0f * EXTENTF));
        const float fy = (qy + EXTENTF) * ((float)IMG_H / (2.0f * EXTENTF));
        const int ix = (int)floorf(fx);
        const int iy = (int)floorf(fy);
        OK[r]  = ((unsigned)ix < IMG_W) & ((unsigned)iy < IMG_H);
        PIX[r] = iy * IMG_W + ix;
        VAL[r] = fabsf(dn);
        TPX[r] = tpx; TPY[r] = tpy; TPZ[r] = tpz;
        UX[r] = -dx; UY[r] = -dy; UZ[r] = -dz;
    }

    const int nbox = s_nbox;
    const int ncyl = s_ncyl;
    const int allz = s_allz;

    // ---- Stage 2: occlusion + accumulate, per ray ----
    #pragma unroll
    for (int r = 0; r < RPT; ++r) {
        if (!OK[r]) continue;
        const float tpx = TPX[r], tpy = TPY[r], tpz = TPZ[r];
        const float ux = UX[r], uy = UY[r], uz = UZ[r];
        bool hit = false;

        if (nbox > 0) {
            const float dux = (fabsf(ux) < EPSF) ? EPSF : ux;
            const float duy = (fabsf(uy) < EPSF) ? EPSF : uy;
            const float duz = (fabsf(uz) < EPSF) ? EPSF : uz;
            const float ivx = __fdividef(1.0f, dux);
            const float ivy = __fdividef(1.0f, duy);
            const float ivz = __fdividef(1.0f, duz);
            const float ox = tpx * ivx, oy = tpy * ivy, oz = tpz * ivz;
            for (int b = 0; b < nbox; ++b) {
                const float4 A = sbA[b];
                const float4 B = sbB[b];
                const float t1x = fmaf(A.x, ivx, -ox);
                const float t2x = fmaf(A.w, ivx, -ox);
                const float t1y = fmaf(A.y, ivy, -oy);
                const float t2y = fmaf(B.x, ivy, -oy);
                const float t1z = fmaf(A.z, ivz, -oz);
                const float t2z = fmaf(B.y, ivz, -oz);
                const float tmin = fmaxf(fmaxf(fminf(t1x, t2x), fminf(t1y, t2y)), fminf(t1z, t2z));
                const float tmax = fminf(fminf(fmaxf(t1x, t2x), fmaxf(t1y, t2y)), fmaxf(t1z, t2z));
                if (tmax >= fmaxf(tmin, EPSF)) { hit = true; break; }
            }
        }

        if (!hit) {
            if (allz) {
                const float A2  = ux * ux + uy * uy;
                const float i2a = __fdividef(1.0f, A2 + EPSF);
                for (int c = 0; c < ncyl; ++c) {
                    const float4 cc = scyl[c];
                    const float mx = tpx - cc.x;
                    const float my = tpy - cc.y;
                    const float Bh = mx * ux + my * uy;
                    const float C  = fmaf(mx, mx, my * my) - cc.w;
                    const float d4 = fmaf(Bh, Bh, -A2 * C);
                    if (d4 > 0.0f) {
                        const float sq = sqrtf(d4);
                        const float t1 = (-Bh - sq) * i2a;
                        const float t2 = (-Bh + sq) * i2a;
                        const float oa = tpz - cc.z;
                        const float a1 = fmaf(t1, uz, oa);
                        const float a2 = fmaf(t2, uz, oa);
                        const float L  = scylL[c];
                        const bool h1 = (t1 > EPSF) & (a1 >= 0.0f) & (a1 <= L);
                        const bool h2 = (t2 > EPSF) & (a2 >= 0.0f) & (a2 <= L);
                        if (h1 | h2) { hit = true; break; }
                    }
                }
            } else {
                for (int c = 0; c < NCYL; ++c) {
                    const CylS cc = scg[c];
                    const float ocx = tpx - cc.px;
                    const float ocy = tpy - cc.py;
                    const float ocz = tpz - cc.pz;
                    const float ua  = ux * cc.ax + uy * cc.ay + uz * cc.az;
                    const float oa  = ocx * cc.ax + ocy * cc.ay + ocz * cc.az;
                    const float ocu = ocx * ux + ocy * uy + ocz * uz;
                    const float oc2 = ocx * ocx + ocy * ocy + ocz * ocz;
                    const float A   = 1.0f - ua * ua;
                    const float Bh  = ocu - oa * ua;
                    const float C   = oc2 - oa * oa - cc.r2;
                    const float d4  = fmaf(Bh, Bh, -A * C);
                    if (d4 > 0.0f) {
                        const float sq  = sqrtf(d4);
                        const float i2a = __fdividef(1.0f, A + EPSF);
                        const float t1  = (-Bh - sq) * i2a;
                        const float t2  = (-Bh + sq) * i2a;
                        const float a1  = fmaf(t1, ua, oa);
                        const float a2  = fmaf(t2, ua, oa);
                        const bool h1 = (t1 > EPSF) & (a1 >= 0.0f) & (a1 <= cc.L);
                        const bool h2 = (t2 > EPSF) & (a2 >= 0.0f) & (a2 <= cc.L);
                        if (h1 | h2) { hit = true; break; }
                    }
                }
            }
        }

        if (!hit) atomicAdd(&img[PIX[r]], VAL[r]);
    }
}

extern "C" void kernel_launch(void* const* d_in, const int* in_sizes, int n_in,
                              void* d_out, int out_size) {
    const float* sources = (const float*)d_in[0];
    const float* mpts    = (const float*)d_in[1];
    const float* mnrm    = (const float*)d_in[2];
    const float* mpos    = (const float*)d_in[3];
    const float* mrot    = (const float*)d_in[4];
    const float* cyl_p1  = (const float*)d_in[5];
    const float* cyl_p2  = (const float*)d_in[6];
    const float* cyl_r   = (const float*)d_in[7];
    const float* box_p1  = (const float*)d_in[8];
    const float* box_p2  = (const float*)d_in[9];
    const float* spos    = (const float*)d_in[10];
    const float* snrm    = (const float*)d_in[11];
    float* img = (float*)d_out;

    cudaMemsetAsync(img, 0, (size_t)out_size * sizeof(float), 0);

    transform_kernel<<<NPTS_TOTAL / TPB, TPB>>>(mpts, mnrm, mpos, mrot);

    render_kernel<<<TOTAL_RAYS / RPB, TPB>>>(sources, mpos,
                                             cyl_p1, cyl_p2, cyl_r,
                                             box_p1, box_p2,
                                             spos, snrm, img);
}